// round 2
// baseline (speedup 1.0000x reference)
#include <cuda_runtime.h>
#include <cstdint>
#include <cstddef>

// ---------------- compile-time bounds (instance: B=16, Lmax=1984, N=24064, D=512) ----
#define LMAX     2048
#define SEGMAX   16
#define BMAX     64
#define NTOK_MAX 32768
#define DMAX     512

#define BM 64
#define BN 64
#define BK 16
#define PAD 4

// ---------------- device scratch (no allocations allowed) ----------------
__device__ float g_x[(size_t)NTOK_MAX * DMAX];                  // projected features x = hW^T+b
__device__ float g_scores[(size_t)SEGMAX * LMAX * LMAX];        // per-segment score/prob matrices
__device__ int   g_len[BMAX];
__device__ int   g_off[BMAX];

// ---------------- segment offsets (handles int32 or int64 lengths buffer) ----------
__global__ void offsets_kernel(const int* __restrict__ lens_raw, int count, int ntok) {
    if (threadIdx.x != 0 || blockIdx.x != 0) return;
    // int64 little-endian looks like [v0,0,v1,0,...] when viewed as int32
    bool is64 = (count >= 2) && (lens_raw[1] == 0) && (lens_raw[0] != 0);
    int acc = 0;
    for (int i = 0; i < BMAX; i++) {
        int L = 0;
        if (i < count && acc < ntok) L = lens_raw[is64 ? 2 * i : i];
        if (L < 0) L = 0;
        if (L > LMAX) L = LMAX;
        g_len[i] = L;
        g_off[i] = acc;
        acc += L;
    }
}

// ---------------- shared NT micro-kernel body: C = A * B^T (+bias) -----------------
// A: M x K (lda), B: N x K (ldb), C: M x N (ldc). 256 threads, 4x4 microtile.
__device__ __forceinline__ void gemm_nt_body(
    const float* __restrict__ A, const float* __restrict__ B,
    float* __restrict__ C, const float* __restrict__ bias,
    int M, int N, int K, int lda, int ldb, int ldc,
    int row0, int col0)
{
    __shared__ float As[BK][BM + PAD];
    __shared__ float Bs[BK][BN + PAD];
    const int tid = threadIdx.x;
    const int tx = tid & 15, ty = tid >> 4;
    float acc[4][4] = {};

    for (int k0 = 0; k0 < K; k0 += BK) {
        #pragma unroll
        for (int i = tid; i < BM * BK; i += 256) {
            int m = i >> 4, k = i & 15;
            int gr = row0 + m, gk = k0 + k;
            As[k][m] = (gr < M && gk < K) ? A[(size_t)gr * lda + gk] : 0.f;
        }
        #pragma unroll
        for (int i = tid; i < BN * BK; i += 256) {
            int n = i >> 4, k = i & 15;
            int gc = col0 + n, gk = k0 + k;
            Bs[k][n] = (gc < N && gk < K) ? B[(size_t)gc * ldb + gk] : 0.f;
        }
        __syncthreads();
        #pragma unroll
        for (int k = 0; k < BK; k++) {
            float a[4], bv[4];
            #pragma unroll
            for (int i = 0; i < 4; i++) a[i] = As[k][ty * 4 + i];
            #pragma unroll
            for (int j = 0; j < 4; j++) bv[j] = Bs[k][tx * 4 + j];
            #pragma unroll
            for (int i = 0; i < 4; i++)
                #pragma unroll
                for (int j = 0; j < 4; j++)
                    acc[i][j] += a[i] * bv[j];
        }
        __syncthreads();
    }

    #pragma unroll
    for (int i = 0; i < 4; i++) {
        int gr = row0 + ty * 4 + i;
        if (gr >= M) continue;
        #pragma unroll
        for (int j = 0; j < 4; j++) {
            int gc = col0 + tx * 4 + j;
            if (gc >= N) continue;
            float v = acc[i][j];
            if (bias) v += bias[gc];
            C[(size_t)gr * ldc + gc] = v;
        }
    }
}

// ---------------- kernel 1: x = h @ W^T + b ----------------
__global__ void linear_kernel(const float* __restrict__ h, const float* __restrict__ W,
                              const float* __restrict__ bias, int Ntok, int D)
{
    gemm_nt_body(h, W, g_x, bias, Ntok, D, D, D, D, D,
                 blockIdx.x * BM, blockIdx.y * BN);
}

// ---------------- kernel 2: per-segment S = Z Y^T ----------------
__global__ void scores_kernel(const float* __restrict__ h, int D)
{
    int b = blockIdx.z;
    int L = g_len[b];
    int row0 = blockIdx.y * BM;
    int col0 = blockIdx.x * BN;
    if (L == 0 || row0 >= L || col0 >= L) return;
    int off = g_off[b];
    const float* Z = h + (size_t)off * D;
    const float* Y = g_x + (size_t)off * D;
    float* S = g_scores + (size_t)b * LMAX * LMAX;
    gemm_nt_body(Z, Y, S, nullptr, L, L, D, D, D, LMAX, row0, col0);
}

// ---------------- kernel 3: row softmax over valid keys ----------------
__global__ void softmax_kernel()
{
    int b = blockIdx.y;
    int l = blockIdx.x;
    int L = g_len[b];
    if (l >= L) return;
    float* row = g_scores + (size_t)b * LMAX * LMAX + (size_t)l * LMAX;
    int tid = threadIdx.x;

    float v[LMAX / 256];
    float mx = -1e30f;
    #pragma unroll
    for (int i = 0; i < LMAX / 256; i++) {
        int m = tid + i * 256;
        v[i] = (m < L) ? row[m] : -1e30f;
        mx = fmaxf(mx, v[i]);
    }
    __shared__ float red[256];
    red[tid] = mx; __syncthreads();
    #pragma unroll
    for (int s = 128; s > 0; s >>= 1) {
        if (tid < s) red[tid] = fmaxf(red[tid], red[tid + s]);
        __syncthreads();
    }
    mx = red[0]; __syncthreads();

    float sum = 0.f;
    #pragma unroll
    for (int i = 0; i < LMAX / 256; i++) {
        int m = tid + i * 256;
        v[i] = (m < L) ? __expf(v[i] - mx) : 0.f;
        sum += v[i];
    }
    red[tid] = sum; __syncthreads();
    #pragma unroll
    for (int s = 128; s > 0; s >>= 1) {
        if (tid < s) red[tid] += red[tid + s];
        __syncthreads();
    }
    float inv = 1.f / red[0];

    #pragma unroll
    for (int i = 0; i < LMAX / 256; i++) {
        int m = tid + i * 256;
        if (m < L) row[m] = v[i] * inv;
    }
}

// ---------------- kernel 4: O = P Z, written to packed output ----------------
__global__ void out_kernel(const float* __restrict__ h, float* __restrict__ out, int D)
{
    int b = blockIdx.z;
    int L = g_len[b];
    if (L == 0) return;
    int row0 = blockIdx.y * BM;
    if (row0 >= L) return;
    int col0 = blockIdx.x * BN;
    int off = g_off[b];
    const float* P = g_scores + (size_t)b * LMAX * LMAX;
    const float* Z = h + (size_t)off * D;

    __shared__ float As[BK][BM + PAD];
    __shared__ float Bs[BK][BN + PAD];
    const int tid = threadIdx.x;
    const int tx = tid & 15, ty = tid >> 4;
    float acc[4][4] = {};

    for (int k0 = 0; k0 < L; k0 += BK) {
        #pragma unroll
        for (int i = tid; i < BM * BK; i += 256) {
            int m = i >> 4, k = i & 15;
            int gr = row0 + m, gk = k0 + k;
            As[k][m] = (gr < L && gk < L) ? P[(size_t)gr * LMAX + gk] : 0.f;
        }
        #pragma unroll
        for (int i = tid; i < BK * BN; i += 256) {
            int k = i >> 6, n = i & 63;   // coalesced over n (BN=64)
            int gk = k0 + k;
            Bs[k][n] = (gk < L) ? Z[(size_t)gk * D + col0 + n] : 0.f;
        }
        __syncthreads();
        #pragma unroll
        for (int k = 0; k < BK; k++) {
            float a[4], bv[4];
            #pragma unroll
            for (int i = 0; i < 4; i++) a[i] = As[k][ty * 4 + i];
            #pragma unroll
            for (int j = 0; j < 4; j++) bv[j] = Bs[k][tx * 4 + j];
            #pragma unroll
            for (int i = 0; i < 4; i++)
                #pragma unroll
                for (int j = 0; j < 4; j++)
                    acc[i][j] += a[i] * bv[j];
        }
        __syncthreads();
    }

    #pragma unroll
    for (int i = 0; i < 4; i++) {
        int gr = row0 + ty * 4 + i;
        if (gr >= L) continue;
        #pragma unroll
        for (int j = 0; j < 4; j++) {
            out[(size_t)(off + gr) * D + col0 + tx * 4 + j] = acc[i][j];
        }
    }
}

// ---------------- launch ----------------
extern "C" void kernel_launch(void* const* d_in, const int* in_sizes, int n_in,
                              void* d_out, int out_size)
{
    const float* h    = (const float*)d_in[0];
    const float* W    = (const float*)d_in[1];
    const float* bias = (const float*)d_in[2];
    const int*   lens = (const int*)d_in[3];

    int D    = in_sizes[2];            // bias length = feature dim (512)
    int Ntok = in_sizes[0] / D;        // packed token count (24064)
    int B    = in_sizes[3];            // segment count (16; may be 2x if int64 counted as words)
    if (B > BMAX) B = BMAX;

    offsets_kernel<<<1, 32>>>(lens, B, Ntok);

    dim3 blk(256);
    dim3 g1((Ntok + BM - 1) / BM, (D + BN - 1) / BN);
    linear_kernel<<<g1, blk>>>(h, W, bias, Ntok, D);

    dim3 g2(LMAX / BN, LMAX / BM, B);
    scores_kernel<<<g2, blk>>>(h, D);

    softmax_kernel<<<dim3(LMAX, B), 256>>>();

    dim3 g3((D + BN - 1) / BN, LMAX / BM, B);
    out_kernel<<<g3, blk>>>(h, (float*)d_out, D);
}

// round 5
// speedup vs baseline: 3.6599x; 3.6599x over previous
#include <cuda_runtime.h>
#include <cuda_bf16.h>
#include <cstdint>
#include <cstddef>

// ---------------- instance bounds (B=16, Lmax=1984, N=24064, D=512) ----------------
#define LMAX     2048
#define SEGMAX   16
#define BMAX     64
#define NTOK_MAX 32768
#define DFIX     512

// ---------------- device scratch (fp32, like the passing R2 kernel) ----------------
__device__ float g_S[(size_t)SEGMAX * LMAX * LMAX];   // scores then probs (in place)
__device__ float g_x[(size_t)NTOK_MAX * DFIX];        // x = h W^T + b
__device__ __nv_bfloat16 g_zThi[(size_t)DFIX * NTOK_MAX];  // h^T split (d-major)
__device__ __nv_bfloat16 g_zTlo[(size_t)DFIX * NTOK_MAX];
__device__ int g_len[BMAX];
__device__ int g_off[BMAX];

// ---------------- helpers ----------------
__device__ __forceinline__ void mma16816(float* c, const uint32_t* a, const uint32_t* b) {
    asm volatile(
        "mma.sync.aligned.m16n8k16.row.col.f32.bf16.bf16.f32 "
        "{%0,%1,%2,%3}, {%4,%5,%6,%7}, {%8,%9}, {%0,%1,%2,%3};"
        : "+f"(c[0]), "+f"(c[1]), "+f"(c[2]), "+f"(c[3])
        : "r"(a[0]), "r"(a[1]), "r"(a[2]), "r"(a[3]), "r"(b[0]), "r"(b[1]));
}
__device__ __forceinline__ void split_f32(float v, __nv_bfloat16& hi, __nv_bfloat16& lo) {
    hi = __float2bfloat16(v);
    lo = __float2bfloat16(v - __bfloat162float(hi));
}

// smem: BK=16 slabs, row stride 24 bf16 (48 B, conflict-free for frag loads)
#define SKP 24
#define SLAB_ELEMS (128 * SKP)   // 3072 bf16 = 6144 B

// ---------------- HMMA NT GEMM core: D[128,128] = A[128,K] * B[128,K]^T ------------
// A fp32 (split on the fly). B either fp32 or pre-split bf16 (BPRE).
// 256 threads = 8 warps (2m x 4n), 64x32 per warp, K multiple of 16.
template <bool BPRE, class Epi>
__device__ __forceinline__ void gemm_core(
    const float* __restrict__ Af, int lda, int Mv,
    const float* __restrict__ Bf,
    const __nv_bfloat16* __restrict__ Bhi, const __nv_bfloat16* __restrict__ Blo,
    int ldb, int Nv, int K, Epi epi)
{
    __shared__ __align__(16) __nv_bfloat16 sm[2][4][SLAB_ELEMS];  // 49152 B
    const int tid  = threadIdx.x;
    const int wid  = tid >> 5, lane = tid & 31;
    const int g    = lane >> 2, tg = lane & 3;
    const int wm   = (wid >> 2) * 64;
    const int wn   = (wid & 3) * 32;

    float C[4][4][4];
    #pragma unroll
    for (int i = 0; i < 4; i++)
        #pragma unroll
        for (int j = 0; j < 4; j++)
            #pragma unroll
            for (int k = 0; k < 4; k++) C[i][j][k] = 0.f;

    float4 ra[2], rbf[2];
    uint4  rbh, rbl;

    auto load_slab = [&](int s) {
        const int k0 = s << 4;
        #pragma unroll
        for (int it = 0; it < 2; it++) {            // A: 128 rows x 4 float4 chunks
            int idx = tid + it * 256;
            int r = idx >> 2, q = idx & 3;
            ra[it] = (r < Mv) ? *(const float4*)(Af + (size_t)r * lda + k0 + q * 4)
                              : make_float4(0.f, 0.f, 0.f, 0.f);
        }
        if (!BPRE) {
            #pragma unroll
            for (int it = 0; it < 2; it++) {
                int idx = tid + it * 256;
                int r = idx >> 2, q = idx & 3;
                rbf[it] = (r < Nv) ? *(const float4*)(Bf + (size_t)r * ldb + k0 + q * 4)
                                   : make_float4(0.f, 0.f, 0.f, 0.f);
            }
        } else {
            int r = tid >> 1, q = tid & 1;          // B: 128 rows x 2 uint4 (8 bf16) chunks
            if (r < Nv) {
                rbh = *(const uint4*)(Bhi + (size_t)r * ldb + k0 + q * 8);
                rbl = *(const uint4*)(Blo + (size_t)r * ldb + k0 + q * 8);
            } else {
                rbh = make_uint4(0u, 0u, 0u, 0u); rbl = rbh;
            }
        }
    };

    auto store_f4 = [&](__nv_bfloat16* hi, __nv_bfloat16* lo, int r, int q, float4 v) {
        __nv_bfloat16 h0, l0, h1, l1, h2, l2, h3, l3;
        split_f32(v.x, h0, l0); split_f32(v.y, h1, l1);
        split_f32(v.z, h2, l2); split_f32(v.w, h3, l3);
        int e = r * SKP + q * 4;
        *(__nv_bfloat162*)(hi + e)     = __halves2bfloat162(h0, h1);
        *(__nv_bfloat162*)(hi + e + 2) = __halves2bfloat162(h2, h3);
        *(__nv_bfloat162*)(lo + e)     = __halves2bfloat162(l0, l1);
        *(__nv_bfloat162*)(lo + e + 2) = __halves2bfloat162(l2, l3);
    };

    auto store_slab = [&](int buf) {
        #pragma unroll
        for (int it = 0; it < 2; it++) {
            int idx = tid + it * 256;
            store_f4(sm[buf][0], sm[buf][1], idx >> 2, idx & 3, ra[it]);
        }
        if (!BPRE) {
            #pragma unroll
            for (int it = 0; it < 2; it++) {
                int idx = tid + it * 256;
                store_f4(sm[buf][2], sm[buf][3], idx >> 2, idx & 3, rbf[it]);
            }
        } else {
            int r = tid >> 1, q = tid & 1;
            *(uint4*)(&sm[buf][2][r * SKP + q * 8]) = rbh;
            *(uint4*)(&sm[buf][3][r * SKP + q * 8]) = rbl;
        }
    };

    const int slabs = K >> 4;
    load_slab(0);
    store_slab(0);
    __syncthreads();

    for (int s = 0; s < slabs; s++) {
        const bool more = (s + 1 < slabs);
        if (more) load_slab(s + 1);                 // global loads overlap compute

        const __nv_bfloat16* sAhi = sm[s & 1][0];
        const __nv_bfloat16* sAlo = sm[s & 1][1];
        const __nv_bfloat16* sBhi = sm[s & 1][2];
        const __nv_bfloat16* sBlo = sm[s & 1][3];
        const int c0 = 2 * tg;

        uint32_t ah[4][4], al[4][4], bh[4][2], bl[4][2];
        #pragma unroll
        for (int mt = 0; mt < 4; mt++) {
            int r0 = wm + mt * 16 + g;
            ah[mt][0] = *(const uint32_t*)(sAhi + r0 * SKP + c0);
            ah[mt][1] = *(const uint32_t*)(sAhi + (r0 + 8) * SKP + c0);
            ah[mt][2] = *(const uint32_t*)(sAhi + r0 * SKP + c0 + 8);
            ah[mt][3] = *(const uint32_t*)(sAhi + (r0 + 8) * SKP + c0 + 8);
            al[mt][0] = *(const uint32_t*)(sAlo + r0 * SKP + c0);
            al[mt][1] = *(const uint32_t*)(sAlo + (r0 + 8) * SKP + c0);
            al[mt][2] = *(const uint32_t*)(sAlo + r0 * SKP + c0 + 8);
            al[mt][3] = *(const uint32_t*)(sAlo + (r0 + 8) * SKP + c0 + 8);
        }
        #pragma unroll
        for (int nt = 0; nt < 4; nt++) {
            int n0 = wn + nt * 8 + g;
            bh[nt][0] = *(const uint32_t*)(sBhi + n0 * SKP + c0);
            bh[nt][1] = *(const uint32_t*)(sBhi + n0 * SKP + c0 + 8);
            bl[nt][0] = *(const uint32_t*)(sBlo + n0 * SKP + c0);
            bl[nt][1] = *(const uint32_t*)(sBlo + n0 * SKP + c0 + 8);
        }
        #pragma unroll
        for (int mt = 0; mt < 4; mt++)
            #pragma unroll
            for (int nt = 0; nt < 4; nt++) {
                mma16816(C[mt][nt], ah[mt], bh[nt]);   // hi*hi
                mma16816(C[mt][nt], ah[mt], bl[nt]);   // hi*lo
                mma16816(C[mt][nt], al[mt], bh[nt]);   // lo*hi
            }

        if (more) store_slab((s + 1) & 1);          // other buffer: safe w/o pre-sync
        __syncthreads();
    }

    #pragma unroll
    for (int mt = 0; mt < 4; mt++)
        #pragma unroll
        for (int nt = 0; nt < 4; nt++)
            epi(wm + mt * 16 + g, wn + nt * 8 + 2 * tg, C[mt][nt]);
}

// ---------------- offsets (int32/int64 lengths) ----------------
__global__ void offsets_kernel(const int* __restrict__ lens_raw, int count, int ntok) {
    if (threadIdx.x != 0 || blockIdx.x != 0) return;
    bool is64 = (count >= 2) && (lens_raw[1] == 0) && (lens_raw[0] != 0);
    int acc = 0;
    for (int i = 0; i < BMAX; i++) {
        int L = 0;
        if (i < count && acc < ntok) L = lens_raw[is64 ? 2 * i : i];
        if (L < 0) L = 0;
        if (L > LMAX) L = LMAX;
        g_len[i] = L; g_off[i] = acc; acc += L;
    }
}

// ---------------- transpose + split: h[N,512] -> zT[512, NTOK_MAX] ----------------
__global__ void transpose_split(const float* __restrict__ h, int Ntok) {
    __shared__ float t[32][33];
    int d0 = blockIdx.x * 32, n0 = blockIdx.y * 32;
    for (int i = threadIdx.y; i < 32; i += 8) {
        int n = n0 + i;
        t[i][threadIdx.x] = (n < Ntok) ? h[(size_t)n * DFIX + d0 + threadIdx.x] : 0.f;
    }
    __syncthreads();
    for (int i = threadIdx.y; i < 32; i += 8) {
        int d = d0 + i, n = n0 + threadIdx.x;
        if (n >= NTOK_MAX) continue;
        float v = t[threadIdx.x][i];
        __nv_bfloat16 hi, lo; split_f32(v, hi, lo);
        g_zThi[(size_t)d * NTOK_MAX + n] = hi;
        g_zTlo[(size_t)d * NTOK_MAX + n] = lo;
    }
}

// ---------------- GEMM 1: x = h W^T + b ----------------
__global__ __launch_bounds__(256)
void linear_gemm(const float* __restrict__ h, const float* __restrict__ W,
                 const float* __restrict__ bias, int Ntok)
{
    int col0 = blockIdx.x * 128, row0 = blockIdx.y * 128;
    if (row0 >= Ntok) return;
    int Mv = Ntok - row0; if (Mv > 128) Mv = 128;
    auto epi = [&](int gm, int gn, const float* c) {
        int gcol = col0 + gn;
        float b0 = bias[gcol], b1 = bias[gcol + 1];
        #pragma unroll
        for (int half = 0; half < 2; half++) {
            int grow = row0 + gm + half * 8;
            if (grow >= Ntok) continue;
            *(float2*)(g_x + (size_t)grow * DFIX + gcol) =
                make_float2(c[half * 2] + b0, c[half * 2 + 1] + b1);
        }
    };
    gemm_core<false>(h + (size_t)row0 * DFIX, DFIX, Mv,
                     W + (size_t)col0 * DFIX, nullptr, nullptr, DFIX, 128,
                     DFIX, epi);
}

// ---------------- GEMM 2: S = Z Y^T per segment ----------------
__global__ __launch_bounds__(256)
void scores_gemm(const float* __restrict__ h)
{
    int b = blockIdx.z;
    int L = g_len[b];
    int col0 = blockIdx.x * 128, row0 = blockIdx.y * 128;
    if (L == 0 || row0 >= L || col0 >= L) return;
    int off = g_off[b];
    int Mv = L - row0; if (Mv > 128) Mv = 128;
    int Nv = L - col0; if (Nv > 128) Nv = 128;
    float* S = g_S + (size_t)b * LMAX * LMAX;
    auto epi = [&](int gm, int gn, const float* c) {
        if (gn >= Nv) return;
        #pragma unroll
        for (int half = 0; half < 2; half++) {
            int rm = gm + half * 8;
            if (rm >= Mv) continue;
            *(float2*)(S + (size_t)(row0 + rm) * LMAX + col0 + gn) =
                make_float2(c[half * 2], c[half * 2 + 1]);
        }
    };
    gemm_core<false>(h + (size_t)(off + row0) * DFIX, DFIX, Mv,
                     g_x + (size_t)(off + col0) * DFIX, nullptr, nullptr, DFIX, Nv,
                     DFIX, epi);
}

// ---------------- softmax rows (in place, fp32) ----------------
__global__ void softmax_kernel()
{
    int b = blockIdx.y, l = blockIdx.x;
    int L = g_len[b];
    if (l >= L) return;
    float* row = g_S + (size_t)b * LMAX * LMAX + (size_t)l * LMAX;
    int tid = threadIdx.x;

    float v[LMAX / 256];
    float mx = -1e30f;
    #pragma unroll
    for (int i = 0; i < LMAX / 256; i++) {
        int m = tid + i * 256;
        v[i] = (m < L) ? row[m] : -1e30f;
        mx = fmaxf(mx, v[i]);
    }
    __shared__ float red[256];
    red[tid] = mx; __syncthreads();
    #pragma unroll
    for (int s = 128; s > 0; s >>= 1) {
        if (tid < s) red[tid] = fmaxf(red[tid], red[tid + s]);
        __syncthreads();
    }
    mx = red[0]; __syncthreads();

    float sum = 0.f;
    #pragma unroll
    for (int i = 0; i < LMAX / 256; i++) {
        int m = tid + i * 256;
        v[i] = (m < L) ? __expf(v[i] - mx) : 0.f;
        sum += v[i];
    }
    red[tid] = sum; __syncthreads();
    #pragma unroll
    for (int s = 128; s > 0; s >>= 1) {
        if (tid < s) red[tid] += red[tid + s];
        __syncthreads();
    }
    float inv = 1.f / red[0];

    #pragma unroll
    for (int i = 0; i < LMAX / 256; i++) {
        int m = tid + i * 256;
        if (m < L) row[m] = v[i] * inv;
    }
}

// ---------------- GEMM 3: out = P Z  (A = P fp32, B = zT pre-split) ----------------
__global__ __launch_bounds__(256)
void out_gemm(float* __restrict__ out)
{
    int b = blockIdx.z;
    int L = g_len[b];
    int col0 = blockIdx.x * 128, row0 = blockIdx.y * 128;
    if (L == 0 || row0 >= L) return;
    int off = g_off[b];
    int Mv = L - row0; if (Mv > 128) Mv = 128;
    auto epi = [&](int gm, int gn, const float* c) {
        #pragma unroll
        for (int half = 0; half < 2; half++) {
            int rm = gm + half * 8;
            if (rm >= Mv) continue;
            *(float2*)(out + (size_t)(off + row0 + rm) * DFIX + col0 + gn) =
                make_float2(c[half * 2], c[half * 2 + 1]);
        }
    };
    gemm_core<true>(g_S + (size_t)b * LMAX * LMAX + (size_t)row0 * LMAX, LMAX, Mv,
                    nullptr,
                    g_zThi + (size_t)col0 * NTOK_MAX + off,
                    g_zTlo + (size_t)col0 * NTOK_MAX + off, NTOK_MAX, 128,
                    L /* K: multiple of 64 */, epi);
}

// ---------------- launch ----------------
extern "C" void kernel_launch(void* const* d_in, const int* in_sizes, int n_in,
                              void* d_out, int out_size)
{
    const float* h    = (const float*)d_in[0];
    const float* W    = (const float*)d_in[1];
    const float* bias = (const float*)d_in[2];
    const int*   lens = (const int*)d_in[3];

    int D    = in_sizes[2];
    int Ntok = in_sizes[0] / D;
    int B    = in_sizes[3];
    if (B > BMAX) B = BMAX;

    offsets_kernel<<<1, 32>>>(lens, B, Ntok);

    transpose_split<<<dim3(DFIX / 32, (Ntok + 31) / 32), dim3(32, 8)>>>(h, Ntok);

    int rowTiles = (Ntok + 127) / 128;
    linear_gemm<<<dim3(DFIX / 128, rowTiles), 256>>>(h, W, bias, Ntok);

    scores_gemm<<<dim3(LMAX / 128, LMAX / 128, B), 256>>>(h);

    softmax_kernel<<<dim3(LMAX, B), 256>>>();

    out_gemm<<<dim3(DFIX / 128, LMAX / 128, B), 256>>>((float*)d_out);
}

// round 9
// speedup vs baseline: 4.1603x; 1.1367x over previous
#include <cuda_runtime.h>
#include <cuda_bf16.h>
#include <cstdint>
#include <cstddef>

// ---------------- instance bounds (B=16, Lmax=1984, N=24064, D=512) ----------------
#define LMAX     2048
#define SEGMAX   16
#define BMAX     64
#define NTOK_MAX 32768
#define DFIX     512

// ---------------- device scratch (EXACTLY the R5 passing layout) ----------------
__device__ float g_S[(size_t)SEGMAX * LMAX * LMAX];   // scores then probs (in place)
__device__ float g_x[(size_t)NTOK_MAX * DFIX];        // x = h W^T + b
__device__ __nv_bfloat16 g_zThi[(size_t)DFIX * NTOK_MAX];  // h^T split (d-major)
__device__ __nv_bfloat16 g_zTlo[(size_t)DFIX * NTOK_MAX];
__device__ int g_len[BMAX];
__device__ int g_off[BMAX];

// ---------------- helpers ----------------
__device__ __forceinline__ uint32_t smem_u32(const void* p) {
    uint32_t a;
    asm("{ .reg .u64 t; cvta.to.shared.u64 t, %1; cvt.u32.u64 %0, t; }" : "=r"(a) : "l"(p));
    return a;
}
__device__ __forceinline__ void ldsm4(uint32_t* r, uint32_t addr) {
    asm volatile("ldmatrix.sync.aligned.m8n8.x4.shared.b16 {%0,%1,%2,%3}, [%4];"
                 : "=r"(r[0]), "=r"(r[1]), "=r"(r[2]), "=r"(r[3]) : "r"(addr));
}
__device__ __forceinline__ void mma16816(float* c, const uint32_t* a, const uint32_t* b) {
    asm volatile(
        "mma.sync.aligned.m16n8k16.row.col.f32.bf16.bf16.f32 "
        "{%0,%1,%2,%3}, {%4,%5,%6,%7}, {%8,%9}, {%0,%1,%2,%3};"
        : "+f"(c[0]), "+f"(c[1]), "+f"(c[2]), "+f"(c[3])
        : "r"(a[0]), "r"(a[1]), "r"(a[2]), "r"(a[3]), "r"(b[0]), "r"(b[1]));
}
__device__ __forceinline__ void split_f32(float v, __nv_bfloat16& hi, __nv_bfloat16& lo) {
    hi = __float2bfloat16(v);
    lo = __float2bfloat16(v - __bfloat162float(hi));
}

// smem: BK=16 slabs, row stride 24 bf16 (48 B, conflict-free for ldmatrix row phases)
#define SKP 24
#define SLAB_ELEMS (128 * SKP)   // 3072 bf16 = 6144 B
#define SLAB_BYTES (SLAB_ELEMS * 2)

// ---------------- HMMA NT GEMM core: D[128,128] = A[128,K] * B[128,K]^T ------------
// A fp32 (split on the fly). B either fp32 or pre-split bf16 (BPRE).
// 256 threads = 8 warps (2m x 4n), 64x32 per warp, K multiple of 16.
// IDENTICAL to the R5 passing kernel except fragment loads use ldmatrix.x4.
template <bool BPRE, class Epi>
__device__ __forceinline__ void gemm_core(
    const float* __restrict__ Af, int lda, int Mv,
    const float* __restrict__ Bf,
    const __nv_bfloat16* __restrict__ Bhi, const __nv_bfloat16* __restrict__ Blo,
    int ldb, int Nv, int K, Epi epi)
{
    __shared__ __align__(16) __nv_bfloat16 sm[2][4][SLAB_ELEMS];  // 49152 B
    const int tid  = threadIdx.x;
    const int wid  = tid >> 5, lane = tid & 31;
    const int g    = lane >> 2, tg = lane & 3;
    const int wm   = (wid >> 2) * 64;
    const int wn   = (wid & 3) * 32;
    const int lrow = lane & 15, lhalf = (lane >> 4) * 8;   // ldmatrix addressing role

    float C[4][4][4];
    #pragma unroll
    for (int i = 0; i < 4; i++)
        #pragma unroll
        for (int j = 0; j < 4; j++)
            #pragma unroll
            for (int k = 0; k < 4; k++) C[i][j][k] = 0.f;

    float4 ra[2], rbf[2];
    uint4  rbh, rbl;

    auto load_slab = [&](int s) {
        const int k0 = s << 4;
        #pragma unroll
        for (int it = 0; it < 2; it++) {            // A: 128 rows x 4 float4 chunks
            int idx = tid + it * 256;
            int r = idx >> 2, q = idx & 3;
            ra[it] = (r < Mv) ? *(const float4*)(Af + (size_t)r * lda + k0 + q * 4)
                              : make_float4(0.f, 0.f, 0.f, 0.f);
        }
        if (!BPRE) {
            #pragma unroll
            for (int it = 0; it < 2; it++) {
                int idx = tid + it * 256;
                int r = idx >> 2, q = idx & 3;
                rbf[it] = (r < Nv) ? *(const float4*)(Bf + (size_t)r * ldb + k0 + q * 4)
                                   : make_float4(0.f, 0.f, 0.f, 0.f);
            }
        } else {
            int r = tid >> 1, q = tid & 1;          // B: 128 rows x 2 uint4 (8 bf16) chunks
            if (r < Nv) {
                rbh = *(const uint4*)(Bhi + (size_t)r * ldb + k0 + q * 8);
                rbl = *(const uint4*)(Blo + (size_t)r * ldb + k0 + q * 8);
            } else {
                rbh = make_uint4(0u, 0u, 0u, 0u); rbl = rbh;
            }
        }
    };

    auto store_f4 = [&](__nv_bfloat16* hi, __nv_bfloat16* lo, int r, int q, float4 v) {
        __nv_bfloat16 h0, l0, h1, l1, h2, l2, h3, l3;
        split_f32(v.x, h0, l0); split_f32(v.y, h1, l1);
        split_f32(v.z, h2, l2); split_f32(v.w, h3, l3);
        int e = r * SKP + q * 4;
        *(__nv_bfloat162*)(hi + e)     = __halves2bfloat162(h0, h1);
        *(__nv_bfloat162*)(hi + e + 2) = __halves2bfloat162(h2, h3);
        *(__nv_bfloat162*)(lo + e)     = __halves2bfloat162(l0, l1);
        *(__nv_bfloat162*)(lo + e + 2) = __halves2bfloat162(l2, l3);
    };

    auto store_slab = [&](int buf) {
        #pragma unroll
        for (int it = 0; it < 2; it++) {
            int idx = tid + it * 256;
            store_f4(sm[buf][0], sm[buf][1], idx >> 2, idx & 3, ra[it]);
        }
        if (!BPRE) {
            #pragma unroll
            for (int it = 0; it < 2; it++) {
                int idx = tid + it * 256;
                store_f4(sm[buf][2], sm[buf][3], idx >> 2, idx & 3, rbf[it]);
            }
        } else {
            int r = tid >> 1, q = tid & 1;
            *(uint4*)(&sm[buf][2][r * SKP + q * 8]) = rbh;
            *(uint4*)(&sm[buf][3][r * SKP + q * 8]) = rbl;
        }
    };

    const int slabs = K >> 4;
    load_slab(0);
    store_slab(0);
    __syncthreads();

    for (int s = 0; s < slabs; s++) {
        const bool more = (s + 1 < slabs);
        if (more) load_slab(s + 1);                 // global loads overlap compute

        const uint32_t sbase = smem_u32(&sm[s & 1][0][0]);
        uint32_t ah[4][4], al[4][4], bfr[2][4], blr[2][4];
        #pragma unroll
        for (int mt = 0; mt < 4; mt++) {
            uint32_t off = (uint32_t)((wm + mt * 16 + lrow) * SKP + lhalf) * 2u;
            ldsm4(ah[mt], sbase + off);
            ldsm4(al[mt], sbase + SLAB_BYTES + off);
        }
        #pragma unroll
        for (int np = 0; np < 2; np++) {            // n pair: covers nt = 2np, 2np+1
            uint32_t off = (uint32_t)((wn + np * 16 + lrow) * SKP + lhalf) * 2u;
            ldsm4(bfr[np], sbase + 2 * SLAB_BYTES + off);
            ldsm4(blr[np], sbase + 3 * SLAB_BYTES + off);
        }
        #pragma unroll
        for (int mt = 0; mt < 4; mt++)
            #pragma unroll
            for (int nt = 0; nt < 4; nt++) {
                int np = nt >> 1, lo = nt & 1;
                uint32_t bh[2] = { bfr[np][lo], bfr[np][lo + 2] };
                uint32_t bl[2] = { blr[np][lo], blr[np][lo + 2] };
                mma16816(C[mt][nt], ah[mt], bh);   // hi*hi
                mma16816(C[mt][nt], ah[mt], bl);   // hi*lo
                mma16816(C[mt][nt], al[mt], bh);   // lo*hi
            }

        if (more) store_slab((s + 1) & 1);          // other buffer: safe w/o pre-sync
        __syncthreads();
    }

    #pragma unroll
    for (int mt = 0; mt < 4; mt++)
        #pragma unroll
        for (int nt = 0; nt < 4; nt++)
            epi(wm + mt * 16 + g, wn + nt * 8 + 2 * tg, C[mt][nt]);
}

// ---------------- offsets (int32/int64 lengths) ----------------
__global__ void offsets_kernel(const int* __restrict__ lens_raw, int count, int ntok) {
    if (threadIdx.x != 0 || blockIdx.x != 0) return;
    bool is64 = (count >= 2) && (lens_raw[1] == 0) && (lens_raw[0] != 0);
    int acc = 0;
    for (int i = 0; i < BMAX; i++) {
        int L = 0;
        if (i < count && acc < ntok) L = lens_raw[is64 ? 2 * i : i];
        if (L < 0) L = 0;
        if (L > LMAX) L = LMAX;
        g_len[i] = L; g_off[i] = acc; acc += L;
    }
}

// ---------------- transpose + split: h[N,512] -> zT[512, NTOK_MAX] ----------------
__global__ void transpose_split(const float* __restrict__ h, int Ntok) {
    __shared__ float t[32][33];
    int d0 = blockIdx.x * 32, n0 = blockIdx.y * 32;
    for (int i = threadIdx.y; i < 32; i += 8) {
        int n = n0 + i;
        t[i][threadIdx.x] = (n < Ntok) ? h[(size_t)n * DFIX + d0 + threadIdx.x] : 0.f;
    }
    __syncthreads();
    for (int i = threadIdx.y; i < 32; i += 8) {
        int d = d0 + i, n = n0 + threadIdx.x;
        if (n >= NTOK_MAX) continue;
        float v = t[threadIdx.x][i];
        __nv_bfloat16 hi, lo; split_f32(v, hi, lo);
        g_zThi[(size_t)d * NTOK_MAX + n] = hi;
        g_zTlo[(size_t)d * NTOK_MAX + n] = lo;
    }
}

// ---------------- GEMM 1: x = h W^T + b ----------------
__global__ __launch_bounds__(256)
void linear_gemm(const float* __restrict__ h, const float* __restrict__ W,
                 const float* __restrict__ bias, int Ntok)
{
    int col0 = blockIdx.x * 128, row0 = blockIdx.y * 128;
    if (row0 >= Ntok) return;
    int Mv = Ntok - row0; if (Mv > 128) Mv = 128;
    auto epi = [&](int gm, int gn, const float* c) {
        int gcol = col0 + gn;
        float b0 = bias[gcol], b1 = bias[gcol + 1];
        #pragma unroll
        for (int half = 0; half < 2; half++) {
            int grow = row0 + gm + half * 8;
            if (grow >= Ntok) continue;
            *(float2*)(g_x + (size_t)grow * DFIX + gcol) =
                make_float2(c[half * 2] + b0, c[half * 2 + 1] + b1);
        }
    };
    gemm_core<false>(h + (size_t)row0 * DFIX, DFIX, Mv,
                     W + (size_t)col0 * DFIX, nullptr, nullptr, DFIX, 128,
                     DFIX, epi);
}

// ---------------- GEMM 2: S = Z Y^T per segment ----------------
__global__ __launch_bounds__(256)
void scores_gemm(const float* __restrict__ h)
{
    int b = blockIdx.z;
    int L = g_len[b];
    int col0 = blockIdx.x * 128, row0 = blockIdx.y * 128;
    if (L == 0 || row0 >= L || col0 >= L) return;
    int off = g_off[b];
    int Mv = L - row0; if (Mv > 128) Mv = 128;
    int Nv = L - col0; if (Nv > 128) Nv = 128;
    float* S = g_S + (size_t)b * LMAX * LMAX;
    auto epi = [&](int gm, int gn, const float* c) {
        if (gn >= Nv) return;
        #pragma unroll
        for (int half = 0; half < 2; half++) {
            int rm = gm + half * 8;
            if (rm >= Mv) continue;
            *(float2*)(S + (size_t)(row0 + rm) * LMAX + col0 + gn) =
                make_float2(c[half * 2], c[half * 2 + 1]);
        }
    };
    gemm_core<false>(h + (size_t)(off + row0) * DFIX, DFIX, Mv,
                     g_x + (size_t)(off + col0) * DFIX, nullptr, nullptr, DFIX, Nv,
                     DFIX, epi);
}

// ---------------- softmax rows (in place, fp32) ----------------
__global__ void softmax_kernel()
{
    int b = blockIdx.y, l = blockIdx.x;
    int L = g_len[b];
    if (l >= L) return;
    float* row = g_S + (size_t)b * LMAX * LMAX + (size_t)l * LMAX;
    int tid = threadIdx.x;

    float v[LMAX / 256];
    float mx = -1e30f;
    #pragma unroll
    for (int i = 0; i < LMAX / 256; i++) {
        int m = tid + i * 256;
        v[i] = (m < L) ? row[m] : -1e30f;
        mx = fmaxf(mx, v[i]);
    }
    __shared__ float red[256];
    red[tid] = mx; __syncthreads();
    #pragma unroll
    for (int s = 128; s > 0; s >>= 1) {
        if (tid < s) red[tid] = fmaxf(red[tid], red[tid + s]);
        __syncthreads();
    }
    mx = red[0]; __syncthreads();

    float sum = 0.f;
    #pragma unroll
    for (int i = 0; i < LMAX / 256; i++) {
        int m = tid + i * 256;
        v[i] = (m < L) ? __expf(v[i] - mx) : 0.f;
        sum += v[i];
    }
    red[tid] = sum; __syncthreads();
    #pragma unroll
    for (int s = 128; s > 0; s >>= 1) {
        if (tid < s) red[tid] += red[tid + s];
        __syncthreads();
    }
    float inv = 1.f / red[0];

    #pragma unroll
    for (int i = 0; i < LMAX / 256; i++) {
        int m = tid + i * 256;
        if (m < L) row[m] = v[i] * inv;
    }
}

// ---------------- GEMM 3: out = P Z  (A = P fp32, B = zT pre-split) ----------------
__global__ __launch_bounds__(256)
void out_gemm(float* __restrict__ out)
{
    int b = blockIdx.z;
    int L = g_len[b];
    int col0 = blockIdx.x * 128, row0 = blockIdx.y * 128;
    if (L == 0 || row0 >= L) return;
    int off = g_off[b];
    int Mv = L - row0; if (Mv > 128) Mv = 128;
    auto epi = [&](int gm, int gn, const float* c) {
        #pragma unroll
        for (int half = 0; half < 2; half++) {
            int rm = gm + half * 8;
            if (rm >= Mv) continue;
            *(float2*)(out + (size_t)(off + row0 + rm) * DFIX + col0 + gn) =
                make_float2(c[half * 2], c[half * 2 + 1]);
        }
    };
    gemm_core<true>(g_S + (size_t)b * LMAX * LMAX + (size_t)row0 * LMAX, LMAX, Mv,
                    nullptr,
                    g_zThi + (size_t)col0 * NTOK_MAX + off,
                    g_zTlo + (size_t)col0 * NTOK_MAX + off, NTOK_MAX, 128,
                    L /* K: multiple of 64 */, epi);
}

// ---------------- launch ----------------
extern "C" void kernel_launch(void* const* d_in, const int* in_sizes, int n_in,
                              void* d_out, int out_size)
{
    const float* h    = (const float*)d_in[0];
    const float* W    = (const float*)d_in[1];
    const float* bias = (const float*)d_in[2];
    const int*   lens = (const int*)d_in[3];

    int D    = in_sizes[2];
    int Ntok = in_sizes[0] / D;
    int B    = in_sizes[3];
    if (B > BMAX) B = BMAX;

    offsets_kernel<<<1, 32>>>(lens, B, Ntok);

    transpose_split<<<dim3(DFIX / 32, (Ntok + 31) / 32), dim3(32, 8)>>>(h, Ntok);

    int rowTiles = (Ntok + 127) / 128;
    linear_gemm<<<dim3(DFIX / 128, rowTiles), 256>>>(h, W, bias, Ntok);

    scores_gemm<<<dim3(LMAX / 128, LMAX / 128, B), 256>>>(h);

    softmax_kernel<<<dim3(LMAX, B), 256>>>();

    out_gemm<<<dim3(DFIX / 128, LMAX / 128, B), 256>>>((float*)d_out);
}